// round 5
// baseline (speedup 1.0000x reference)
#include <cuda_runtime.h>
#include <cuda_bf16.h>
#include <stdint.h>

#define BB 16
#define LLEN 2048
#define DD 64
#define TQ 128
#define NTH 256
#define STRIDE 144               // smem row stride in bytes (72 bf16, conflict-free)

#define OFF_QH 0
#define OFF_QL (128 * STRIDE)
#define OFF_KH (2 * 128 * STRIDE)
#define OFF_KL (OFF_KH + 64 * STRIDE)
#define SMEM_TOTAL (OFF_KL + 64 * STRIDE)   // 55296 bytes
#define OFF_VH 0                 // pass2 V aliases Q region
#define OFF_VL (128 * STRIDE)

#define NEG_INF __int_as_float(0xff800000)

#define PACK_PITCH (LLEN / 16)                         // uint32 words per row
#define PACK_WORDS ((size_t)BB * LLEN * PACK_PITCH)    // 4,194,304 words = 16.8MB
__device__ uint32_t g_packed[PACK_WORDS];

// ---------------- helpers ----------------
__device__ __forceinline__ uint32_t smem_u32(const void* p) {
    uint32_t a;
    asm("{ .reg .u64 t; cvta.to.shared.u64 t, %1; cvt.u32.u64 %0, t; }" : "=r"(a) : "l"(p));
    return a;
}
__device__ __forceinline__ void ldsm4(uint32_t a, uint32_t r[4]) {
    asm volatile("ldmatrix.sync.aligned.m8n8.x4.shared.b16 {%0,%1,%2,%3}, [%4];"
                 : "=r"(r[0]), "=r"(r[1]), "=r"(r[2]), "=r"(r[3]) : "r"(a));
}
__device__ __forceinline__ void ldsm4t(uint32_t a, uint32_t r[4]) {
    asm volatile("ldmatrix.sync.aligned.m8n8.x4.trans.shared.b16 {%0,%1,%2,%3}, [%4];"
                 : "=r"(r[0]), "=r"(r[1]), "=r"(r[2]), "=r"(r[3]) : "r"(a));
}
__device__ __forceinline__ void mma_bf16(float* d, const uint32_t* a, uint32_t b0, uint32_t b1) {
    asm volatile("mma.sync.aligned.m16n8k16.row.col.f32.bf16.bf16.f32 "
                 "{%0,%1,%2,%3}, {%4,%5,%6,%7}, {%8,%9}, {%0,%1,%2,%3};"
                 : "+f"(d[0]), "+f"(d[1]), "+f"(d[2]), "+f"(d[3])
                 : "r"(a[0]), "r"(a[1]), "r"(a[2]), "r"(a[3]), "r"(b0), "r"(b1));
}
__device__ __forceinline__ void split2(float a, float b, uint32_t& hi, uint32_t& lo) {
    __nv_bfloat16 ah = __float2bfloat16(a);
    __nv_bfloat16 bh = __float2bfloat16(b);
    float ar = a - __bfloat162float(ah);
    float br = b - __bfloat162float(bh);
    __nv_bfloat162 H; H.x = ah; H.y = bh;
    __nv_bfloat162 L; L.x = __float2bfloat16(ar); L.y = __float2bfloat16(br);
    hi = *reinterpret_cast<uint32_t*>(&H);
    lo = *reinterpret_cast<uint32_t*>(&L);
}
template <int N4>
__device__ __forceinline__ void load_regs(const float* __restrict__ g, float4* r, int tid) {
    #pragma unroll
    for (int i = 0; i < N4; ++i)
        r[i] = reinterpret_cast<const float4*>(g)[tid + i * NTH];
}
template <int N4>
__device__ __forceinline__ void store_split(const float4* r, char* hi, char* lo,
                                            float scale, int tid) {
    #pragma unroll
    for (int i = 0; i < N4; ++i) {
        int idx = tid + i * NTH;
        float4 t = r[i];
        uint32_t h01, l01, h23, l23;
        split2(t.x * scale, t.y * scale, h01, l01);
        split2(t.z * scale, t.w * scale, h23, l23);
        int rr = idx >> 4;
        int c8 = (idx & 15) << 3;
        *reinterpret_cast<uint2*>(hi + rr * STRIDE + c8) = make_uint2(h01, h23);
        *reinterpret_cast<uint2*>(lo + rr * STRIDE + c8) = make_uint2(l01, l23);
    }
}

// ============ prepack: mask/diag int32 -> 2 bits/element ============
__global__ __launch_bounds__(256)
void prepack_kernel(const int* __restrict__ mask, const int* __restrict__ diag)
{
    size_t w = (size_t)blockIdx.x * 256 + threadIdx.x;   // word index
    const int4* mp = reinterpret_cast<const int4*>(mask) + w * 4;
    const int4* dp = reinterpret_cast<const int4*>(diag) + w * 4;
    uint32_t bits = 0;
    #pragma unroll
    for (int g = 0; g < 4; ++g) {
        int4 m = mp[g];
        int4 d = dp[g];
        int j = g * 8;
        if (m.x)      bits |= 1u << (j + 0);
        if (d.x == 0) bits |= 1u << (j + 1);
        if (m.y)      bits |= 1u << (j + 2);
        if (d.y == 0) bits |= 1u << (j + 3);
        if (m.z)      bits |= 1u << (j + 4);
        if (d.z == 0) bits |= 1u << (j + 5);
        if (m.w)      bits |= 1u << (j + 6);
        if (d.w == 0) bits |= 1u << (j + 7);
    }
    g_packed[w] = bits;
}

// ============ main fused attention ============
__global__ __launch_bounds__(NTH, 2)
void attn_mma_kernel(const float* __restrict__ qg,
                     const float* __restrict__ kg,
                     const float* __restrict__ vg,
                     float* __restrict__ outp,
                     float* __restrict__ attn)
{
    extern __shared__ __align__(16) char smem[];
    const int tid  = threadIdx.x;
    const int wid  = tid >> 5;
    const int lane = tid & 31;
    const int qt   = lane & 3;
    const int b    = blockIdx.y;
    const int q0   = blockIdx.x * TQ;

    const uint32_t sb = smem_u32(smem);
    const float* kbase = kg + (size_t)b * LLEN * DD;
    const float* vbase = vg + (size_t)b * LLEN * DD;

    // Q tile (pre-scaled by 1/temperature) -> QH/QL
    {
        float4 qreg[8];
        load_regs<8>(qg + ((size_t)b * LLEN + q0) * DD, qreg, tid);
        store_split<8>(qreg, smem + OFF_QH, smem + OFF_QL, 0.125f, tid);
    }

    const int r0l = wid * 16 + (lane >> 2);          // this thread's row0 (row1 = +8)
    const size_t g0 = (size_t)b * LLEN + q0 + r0l;
    float* a0p = attn + g0 * LLEN;
    float* a1p = a0p + (size_t)8 * LLEN;
    const uint32_t* pk0 = g_packed + g0 * PACK_PITCH;
    const uint32_t* pk1 = pk0 + (size_t)8 * PACK_PITCH;

    // ldmatrix per-lane address components
    const uint32_t aoff = (uint32_t)((wid * 16 + (lane & 7) + ((lane >> 3) & 1) * 8) * STRIDE
                                     + (lane >> 4) * 16);
    const uint32_t qh_a = sb + OFF_QH + aoff;
    const uint32_t ql_a = sb + OFF_QL + aoff;
    const uint32_t boff = (uint32_t)(((((lane >> 4) & 1) * 8) + (lane & 7)) * STRIDE
                                     + ((lane >> 3) & 1) * 16);
    const uint32_t kh_a = sb + OFF_KH + boff;
    const uint32_t kl_a = sb + OFF_KL + boff;
    const uint32_t voff = (uint32_t)(((((lane >> 3) & 1) * 8) + (lane & 7)) * STRIDE
                                     + ((lane >> 4) & 1) * 16);
    const uint32_t vh_a = sb + OFF_VH + voff;
    const uint32_t vl_a = sb + OFF_VL + voff;

    float m0 = -3.0e38f, m1 = -3.0e38f, l0 = 0.0f, l1 = 0.0f;

    // preload K tile 0
    {
        float4 kreg[4];
        load_regs<4>(kbase, kreg, tid);
        store_split<4>(kreg, smem + OFF_KH, smem + OFF_KL, 1.0f, tid);
    }
    __syncthreads();

    // =========================== PASS 1: S = QK^T, masks, stats ===========================
    for (int kt = 0; kt < 32; ++kt) {
        const int k0 = kt * 64;

        // prefetch next K tile into registers (latency hidden by MMA chain)
        float4 knext[4];
        if (kt + 1 < 32)
            load_regs<4>(kbase + (size_t)(k0 + 64) * DD, knext, tid);
        // prefetch packed mask words for this tile (2 x uint4)
        uint32_t ws0[4], ws1[4];
        {
            uint4 t0 = *reinterpret_cast<const uint4*>(pk0 + (k0 >> 4));
            uint4 t1 = *reinterpret_cast<const uint4*>(pk1 + (k0 >> 4));
            ws0[0] = t0.x; ws0[1] = t0.y; ws0[2] = t0.z; ws0[3] = t0.w;
            ws1[0] = t1.x; ws1[1] = t1.y; ws1[2] = t1.z; ws1[3] = t1.w;
        }

        float acc[8][4];
        #pragma unroll
        for (int nt = 0; nt < 8; ++nt)
            #pragma unroll
            for (int i = 0; i < 4; ++i) acc[nt][i] = 0.0f;

        #pragma unroll
        for (int kc = 0; kc < 4; ++kc) {
            uint32_t ah[4], al[4];
            ldsm4(qh_a + kc * 32, ah);
            ldsm4(ql_a + kc * 32, al);
            #pragma unroll
            for (int p = 0; p < 4; ++p) {
                uint32_t kh4[4], kl4[4];
                ldsm4(kh_a + p * 16 * STRIDE + kc * 32, kh4);
                ldsm4(kl_a + p * 16 * STRIDE + kc * 32, kl4);
                mma_bf16(acc[2 * p],     ah, kh4[0], kh4[1]);
                mma_bf16(acc[2 * p],     ah, kl4[0], kl4[1]);
                mma_bf16(acc[2 * p],     al, kh4[0], kh4[1]);
                mma_bf16(acc[2 * p + 1], ah, kh4[2], kh4[3]);
                mma_bf16(acc[2 * p + 1], ah, kl4[2], kl4[3]);
                mma_bf16(acc[2 * p + 1], al, kh4[2], kh4[3]);
            }
        }
        __syncthreads();                 // all warps done reading K smem
        if (kt + 1 < 32)
            store_split<4>(knext, smem + OFF_KH, smem + OFF_KL, 1.0f, tid);

        // masks (from packed bits) + raw score store + tile max
        float t0 = -3.0e38f, t1 = -3.0e38f;
        #pragma unroll
        for (int nt = 0; nt < 8; ++nt) {
            const int cb = k0 + nt * 8 + qt * 2;
            const int sh = ((nt & 1) * 16) + qt * 4;
            uint32_t bw0 = ws0[nt >> 1] >> sh;
            uint32_t bw1 = ws1[nt >> 1] >> sh;
            float s0 = acc[nt][0], s1 = acc[nt][1], s2 = acc[nt][2], s3 = acc[nt][3];
            if (bw0 & 1u) s0 = NEG_INF;  if (bw0 & 2u) s0 = -1.0e32f;
            if (bw0 & 4u) s1 = NEG_INF;  if (bw0 & 8u) s1 = -1.0e32f;
            if (bw1 & 1u) s2 = NEG_INF;  if (bw1 & 2u) s2 = -1.0e32f;
            if (bw1 & 4u) s3 = NEG_INF;  if (bw1 & 8u) s3 = -1.0e32f;
            *reinterpret_cast<float2*>(a0p + cb) = make_float2(s0, s1);
            *reinterpret_cast<float2*>(a1p + cb) = make_float2(s2, s3);
            acc[nt][0] = s0; acc[nt][1] = s1; acc[nt][2] = s2; acc[nt][3] = s3;
            t0 = fmaxf(t0, fmaxf(s0, s1));
            t1 = fmaxf(t1, fmaxf(s2, s3));
        }
        t0 = fmaxf(t0, __shfl_xor_sync(0xffffffffu, t0, 1));
        t0 = fmaxf(t0, __shfl_xor_sync(0xffffffffu, t0, 2));
        t1 = fmaxf(t1, __shfl_xor_sync(0xffffffffu, t1, 1));
        t1 = fmaxf(t1, __shfl_xor_sync(0xffffffffu, t1, 2));
        const float mn0 = fmaxf(m0, t0);
        const float mn1 = fmaxf(m1, t1);
        float e0 = 0.0f, e1 = 0.0f;
        #pragma unroll
        for (int nt = 0; nt < 8; ++nt) {
            e0 += __expf(acc[nt][0] - mn0) + __expf(acc[nt][1] - mn0);
            e1 += __expf(acc[nt][2] - mn1) + __expf(acc[nt][3] - mn1);
        }
        e0 += __shfl_xor_sync(0xffffffffu, e0, 1);
        e0 += __shfl_xor_sync(0xffffffffu, e0, 2);
        e1 += __shfl_xor_sync(0xffffffffu, e1, 1);
        e1 += __shfl_xor_sync(0xffffffffu, e1, 2);
        l0 = l0 * __expf(m0 - mn0) + e0;  m0 = mn0;
        l1 = l1 * __expf(m1 - mn1) + e1;  m1 = mn1;
        __syncthreads();                 // next K tile visible
    }

    const float rinv0 = 1.0f / l0;
    const float rinv1 = 1.0f / l1;

    float oacc[8][4];
    #pragma unroll
    for (int nt = 0; nt < 8; ++nt)
        #pragma unroll
        for (int i = 0; i < 4; ++i) oacc[nt][i] = 0.0f;

    // preload V tile 0 (aliases Q region; pass-1 reads of Q ended before last sync)
    {
        float4 vreg[8];
        load_regs<8>(vbase, vreg, tid);
        store_split<8>(vreg, smem + OFF_VH, smem + OFF_VL, 1.0f, tid);
    }
    __syncthreads();

    // =========================== PASS 2: attn probs + O = P V ===========================
    for (int kt = 0; kt < 16; ++kt) {
        const int k0 = kt * 128;

        float4 vnext[8];
        if (kt + 1 < 16)
            load_regs<8>(vbase + (size_t)(k0 + 128) * DD, vnext, tid);

        #pragma unroll
        for (int kc = 0; kc < 8; ++kc) {
            const int cb = k0 + kc * 16 + qt * 2;
            float2 x0  = *reinterpret_cast<const float2*>(a0p + cb);
            float2 x0h = *reinterpret_cast<const float2*>(a0p + cb + 8);
            float2 x1  = *reinterpret_cast<const float2*>(a1p + cb);
            float2 x1h = *reinterpret_cast<const float2*>(a1p + cb + 8);
            float p00 = __expf(x0.x  - m0) * rinv0;
            float p01 = __expf(x0.y  - m0) * rinv0;
            float p02 = __expf(x0h.x - m0) * rinv0;
            float p03 = __expf(x0h.y - m0) * rinv0;
            float p10 = __expf(x1.x  - m1) * rinv1;
            float p11 = __expf(x1.y  - m1) * rinv1;
            float p12 = __expf(x1h.x - m1) * rinv1;
            float p13 = __expf(x1h.y - m1) * rinv1;
            *reinterpret_cast<float2*>(a0p + cb)     = make_float2(p00, p01);
            *reinterpret_cast<float2*>(a0p + cb + 8) = make_float2(p02, p03);
            *reinterpret_cast<float2*>(a1p + cb)     = make_float2(p10, p11);
            *reinterpret_cast<float2*>(a1p + cb + 8) = make_float2(p12, p13);

            uint32_t ah[4], al[4];
            split2(p00, p01, ah[0], al[0]);   // row0, k-lo
            split2(p10, p11, ah[1], al[1]);   // row1, k-lo
            split2(p02, p03, ah[2], al[2]);   // row0, k-hi
            split2(p12, p13, ah[3], al[3]);   // row1, k-hi

            #pragma unroll
            for (int p = 0; p < 4; ++p) {
                uint32_t vh4[4], vl4[4];
                ldsm4t(vh_a + kc * 16 * STRIDE + p * 32, vh4);
                ldsm4t(vl_a + kc * 16 * STRIDE + p * 32, vl4);
                mma_bf16(oacc[2 * p],     ah, vh4[0], vh4[1]);
                mma_bf16(oacc[2 * p],     ah, vl4[0], vl4[1]);
                mma_bf16(oacc[2 * p],     al, vh4[0], vh4[1]);
                mma_bf16(oacc[2 * p + 1], ah, vh4[2], vh4[3]);
                mma_bf16(oacc[2 * p + 1], ah, vl4[2], vl4[3]);
                mma_bf16(oacc[2 * p + 1], al, vh4[2], vh4[3]);
            }
        }
        __syncthreads();                 // all warps done reading V smem
        if (kt + 1 < 16)
            store_split<8>(vnext, smem + OFF_VH, smem + OFF_VL, 1.0f, tid);
        __syncthreads();                 // next V tile visible
    }

    // ---- write output ----
    float* o0 = outp + g0 * DD;
    float* o1 = o0 + (size_t)8 * DD;
    #pragma unroll
    for (int nt = 0; nt < 8; ++nt) {
        const int cb = nt * 8 + qt * 2;
        *reinterpret_cast<float2*>(o0 + cb) = make_float2(oacc[nt][0], oacc[nt][1]);
        *reinterpret_cast<float2*>(o1 + cb) = make_float2(oacc[nt][2], oacc[nt][3]);
    }
}

extern "C" void kernel_launch(void* const* d_in, const int* in_sizes, int n_in,
                              void* d_out, int out_size)
{
    const float* q    = (const float*)d_in[0];
    const float* k    = (const float*)d_in[1];
    const float* v    = (const float*)d_in[2];
    const int*   diag = (const int*)d_in[3];
    const int*   mask = (const int*)d_in[4];

    float* out  = (float*)d_out;                     // [B, L, D]
    float* attn = out + (size_t)BB * LLEN * DD;      // [B, L, L]

    prepack_kernel<<<(unsigned)(PACK_WORDS / 256), 256>>>(mask, diag);

    cudaFuncSetAttribute(attn_mma_kernel,
                         cudaFuncAttributeMaxDynamicSharedMemorySize, SMEM_TOTAL);
    dim3 grid(LLEN / TQ, BB);
    attn_mma_kernel<<<grid, NTH, SMEM_TOTAL>>>(q, k, v, out, attn);
}

// round 6
// speedup vs baseline: 1.0207x; 1.0207x over previous
#include <cuda_runtime.h>
#include <cuda_bf16.h>
#include <stdint.h>

#define BB 16
#define LLEN 2048
#define DD 64
#define TQ 128
#define NTH 256
#define STRIDE 144               // smem row stride in bytes (72 bf16, conflict-free)
#define NROWS (BB * LLEN)        // 32768 global q-rows

#define OFF_QH 0
#define OFF_QL (128 * STRIDE)
#define OFF_KH (256 * STRIDE)
#define OFF_KL (OFF_KH + 64 * STRIDE)
#define OFF_VH (OFF_KH + 128 * STRIDE)
#define OFF_VL (OFF_VH + 64 * STRIDE)
#define SMEM_TOTAL (OFF_VL + 64 * STRIDE)   // 73728 bytes

#define NEG_INF __int_as_float(0xff800000)

// packed mask bits: per (tile kt, row, qt) one uint32 (8 n-tiles x 4 bits)
// index = kt * NROWS*4 + row*4 + qt   -> coalesced writes/reads
__device__ uint32_t g_packed[(size_t)32 * NROWS * 4];   // 16.8 MB

// ---------------- helpers ----------------
__device__ __forceinline__ uint32_t smem_u32(const void* p) {
    uint32_t a;
    asm("{ .reg .u64 t; cvta.to.shared.u64 t, %1; cvt.u32.u64 %0, t; }" : "=r"(a) : "l"(p));
    return a;
}
__device__ __forceinline__ void ldsm4(uint32_t a, uint32_t r[4]) {
    asm volatile("ldmatrix.sync.aligned.m8n8.x4.shared.b16 {%0,%1,%2,%3}, [%4];"
                 : "=r"(r[0]), "=r"(r[1]), "=r"(r[2]), "=r"(r[3]) : "r"(a));
}
__device__ __forceinline__ void ldsm4t(uint32_t a, uint32_t r[4]) {
    asm volatile("ldmatrix.sync.aligned.m8n8.x4.trans.shared.b16 {%0,%1,%2,%3}, [%4];"
                 : "=r"(r[0]), "=r"(r[1]), "=r"(r[2]), "=r"(r[3]) : "r"(a));
}
__device__ __forceinline__ void mma_bf16(float* d, const uint32_t* a, uint32_t b0, uint32_t b1) {
    asm volatile("mma.sync.aligned.m16n8k16.row.col.f32.bf16.bf16.f32 "
                 "{%0,%1,%2,%3}, {%4,%5,%6,%7}, {%8,%9}, {%0,%1,%2,%3};"
                 : "+f"(d[0]), "+f"(d[1]), "+f"(d[2]), "+f"(d[3])
                 : "r"(a[0]), "r"(a[1]), "r"(a[2]), "r"(a[3]), "r"(b0), "r"(b1));
}
__device__ __forceinline__ void split2(float a, float b, uint32_t& hi, uint32_t& lo) {
    __nv_bfloat16 ah = __float2bfloat16(a);
    __nv_bfloat16 bh = __float2bfloat16(b);
    float ar = a - __bfloat162float(ah);
    float br = b - __bfloat162float(bh);
    __nv_bfloat162 H; H.x = ah; H.y = bh;
    __nv_bfloat162 L; L.x = __float2bfloat16(ar); L.y = __float2bfloat16(br);
    hi = *reinterpret_cast<uint32_t*>(&H);
    lo = *reinterpret_cast<uint32_t*>(&L);
}
template <int N4>
__device__ __forceinline__ void load_regs(const float* __restrict__ g, float4* r, int tid) {
    #pragma unroll
    for (int i = 0; i < N4; ++i)
        r[i] = reinterpret_cast<const float4*>(g)[tid + i * NTH];
}
template <int N4>
__device__ __forceinline__ void store_split(const float4* r, char* hi, char* lo,
                                            float scale, int tid) {
    #pragma unroll
    for (int i = 0; i < N4; ++i) {
        int idx = tid + i * NTH;
        float4 t = r[i];
        uint32_t h01, l01, h23, l23;
        split2(t.x * scale, t.y * scale, h01, l01);
        split2(t.z * scale, t.w * scale, h23, l23);
        int rr = idx >> 4;
        int c8 = (idx & 15) << 3;
        *reinterpret_cast<uint2*>(hi + rr * STRIDE + c8) = make_uint2(h01, h23);
        *reinterpret_cast<uint2*>(lo + rr * STRIDE + c8) = make_uint2(l01, l23);
    }
}
// apply 4 mask bits (m0,d0,m1,d1) to a score pair
__device__ __forceinline__ void apply_bits(uint32_t bw, float& s0, float& s1) {
    if (bw & 1u) s0 = NEG_INF;
    if (bw & 2u) s0 = -1.0e32f;
    if (bw & 4u) s1 = NEG_INF;
    if (bw & 8u) s1 = -1.0e32f;
}

__global__ __launch_bounds__(NTH, 2)
void attn_mma_kernel(const float* __restrict__ qg,
                     const float* __restrict__ kg,
                     const float* __restrict__ vg,
                     const int* __restrict__ diag,
                     const int* __restrict__ maskb,
                     float* __restrict__ outp,
                     float* __restrict__ attn)
{
    extern __shared__ __align__(16) char smem[];
    const int tid  = threadIdx.x;
    const int wid  = tid >> 5;
    const int lane = tid & 31;
    const int qt   = lane & 3;
    const int b    = blockIdx.y;
    const int q0   = blockIdx.x * TQ;

    const uint32_t sb = smem_u32(smem);
    const float* kbase = kg + (size_t)b * LLEN * DD;
    const float* vbase = vg + (size_t)b * LLEN * DD;

    // Q tile (pre-scaled by 1/temperature) -> QH/QL (persistent, never aliased)
    {
        float4 qreg[8];
        load_regs<8>(qg + ((size_t)b * LLEN + q0) * DD, qreg, tid);
        store_split<8>(qreg, smem + OFF_QH, smem + OFF_QL, 0.125f, tid);
    }

    const int r0l = wid * 16 + (lane >> 2);          // this thread's row0 (row1 = +8)
    const size_t g0 = (size_t)b * LLEN + q0 + r0l;
    const int* m0p = maskb + g0 * LLEN;
    const int* m1p = m0p + (size_t)8 * LLEN;
    const int* d0p = diag + g0 * LLEN;
    const int* d1p = d0p + (size_t)8 * LLEN;
    float* a0p = attn + g0 * LLEN;
    float* a1p = a0p + (size_t)8 * LLEN;
    const size_t pc0 = g0 * 4 + qt;                  // packed idx const part, row0
    const size_t pc1 = (g0 + 8) * 4 + qt;            // row1

    // ldmatrix per-lane address components
    const uint32_t aoff = (uint32_t)((wid * 16 + (lane & 7) + ((lane >> 3) & 1) * 8) * STRIDE
                                     + (lane >> 4) * 16);
    const uint32_t qh_a = sb + OFF_QH + aoff;
    const uint32_t ql_a = sb + OFF_QL + aoff;
    const uint32_t boff = (uint32_t)(((((lane >> 4) & 1) * 8) + (lane & 7)) * STRIDE
                                     + ((lane >> 3) & 1) * 16);
    const uint32_t kh_a = sb + OFF_KH + boff;
    const uint32_t kl_a = sb + OFF_KL + boff;
    const uint32_t voff = (uint32_t)(((((lane >> 3) & 1) * 8) + (lane & 7)) * STRIDE
                                     + ((lane >> 4) & 1) * 16);
    const uint32_t vh_a = sb + OFF_VH + voff;
    const uint32_t vl_a = sb + OFF_VL + voff;

    float m0 = -3.0e38f, m1 = -3.0e38f, l0 = 0.0f, l1 = 0.0f;

    // preload K tile 0
    {
        float4 kreg[4];
        load_regs<4>(kbase, kreg, tid);
        store_split<4>(kreg, smem + OFF_KH, smem + OFF_KL, 1.0f, tid);
    }
    __syncthreads();

    // ============ PASS 1: S = QK^T, read+pack masks, online stats (no attn writes) ============
    for (int kt = 0; kt < 32; ++kt) {
        const int k0 = kt * 64;

        float4 knext[4];
        if (kt + 1 < 32)
            load_regs<4>(kbase + (size_t)(k0 + 64) * DD, knext, tid);

        float acc[8][4];
        #pragma unroll
        for (int nt = 0; nt < 8; ++nt)
            #pragma unroll
            for (int i = 0; i < 4; ++i) acc[nt][i] = 0.0f;

        #pragma unroll
        for (int kc = 0; kc < 4; ++kc) {
            uint32_t ah[4], al[4];
            ldsm4(qh_a + kc * 32, ah);
            ldsm4(ql_a + kc * 32, al);
            #pragma unroll
            for (int p = 0; p < 4; ++p) {
                uint32_t kh4[4], kl4[4];
                ldsm4(kh_a + p * 16 * STRIDE + kc * 32, kh4);
                ldsm4(kl_a + p * 16 * STRIDE + kc * 32, kl4);
                mma_bf16(acc[2 * p],     ah, kh4[0], kh4[1]);
                mma_bf16(acc[2 * p],     ah, kl4[0], kl4[1]);
                mma_bf16(acc[2 * p],     al, kh4[0], kh4[1]);
                mma_bf16(acc[2 * p + 1], ah, kh4[2], kh4[3]);
                mma_bf16(acc[2 * p + 1], ah, kl4[2], kl4[3]);
                mma_bf16(acc[2 * p + 1], al, kh4[2], kh4[3]);
            }
        }
        __syncthreads();                 // all warps done reading K smem
        if (kt + 1 < 32)
            store_split<4>(knext, smem + OFF_KH, smem + OFF_KL, 1.0f, tid);

        // batched mask/diag loads (high MLP), pack to bits, store, apply
        int2 Am0[8], Ad0[8], Am1[8], Ad1[8];
        #pragma unroll
        for (int nt = 0; nt < 8; ++nt) {
            const int cb = k0 + nt * 8 + qt * 2;
            Am0[nt] = *reinterpret_cast<const int2*>(m0p + cb);
            Ad0[nt] = *reinterpret_cast<const int2*>(d0p + cb);
            Am1[nt] = *reinterpret_cast<const int2*>(m1p + cb);
            Ad1[nt] = *reinterpret_cast<const int2*>(d1p + cb);
        }
        uint32_t w0 = 0, w1 = 0;
        #pragma unroll
        for (int nt = 0; nt < 8; ++nt) {
            const int sh = nt * 4;
            if (Am0[nt].x)      w0 |= 1u << sh;
            if (Ad0[nt].x == 0) w0 |= 2u << sh;
            if (Am0[nt].y)      w0 |= 4u << sh;
            if (Ad0[nt].y == 0) w0 |= 8u << sh;
            if (Am1[nt].x)      w1 |= 1u << sh;
            if (Ad1[nt].x == 0) w1 |= 2u << sh;
            if (Am1[nt].y)      w1 |= 4u << sh;
            if (Ad1[nt].y == 0) w1 |= 8u << sh;
        }
        const size_t pbase = (size_t)kt * (NROWS * 4);
        g_packed[pbase + pc0] = w0;
        g_packed[pbase + pc1] = w1;

        float t0 = -3.0e38f, t1 = -3.0e38f;
        #pragma unroll
        for (int nt = 0; nt < 8; ++nt) {
            const int sh = nt * 4;
            apply_bits(w0 >> sh, acc[nt][0], acc[nt][1]);
            apply_bits(w1 >> sh, acc[nt][2], acc[nt][3]);
            t0 = fmaxf(t0, fmaxf(acc[nt][0], acc[nt][1]));
            t1 = fmaxf(t1, fmaxf(acc[nt][2], acc[nt][3]));
        }
        t0 = fmaxf(t0, __shfl_xor_sync(0xffffffffu, t0, 1));
        t0 = fmaxf(t0, __shfl_xor_sync(0xffffffffu, t0, 2));
        t1 = fmaxf(t1, __shfl_xor_sync(0xffffffffu, t1, 1));
        t1 = fmaxf(t1, __shfl_xor_sync(0xffffffffu, t1, 2));
        const float mn0 = fmaxf(m0, t0);
        const float mn1 = fmaxf(m1, t1);
        float e0 = 0.0f, e1 = 0.0f;
        #pragma unroll
        for (int nt = 0; nt < 8; ++nt) {
            e0 += __expf(acc[nt][0] - mn0) + __expf(acc[nt][1] - mn0);
            e1 += __expf(acc[nt][2] - mn1) + __expf(acc[nt][3] - mn1);
        }
        e0 += __shfl_xor_sync(0xffffffffu, e0, 1);
        e0 += __shfl_xor_sync(0xffffffffu, e0, 2);
        e1 += __shfl_xor_sync(0xffffffffu, e1, 1);
        e1 += __shfl_xor_sync(0xffffffffu, e1, 2);
        l0 = l0 * __expf(m0 - mn0) + e0;  m0 = mn0;
        l1 = l1 * __expf(m1 - mn1) + e1;  m1 = mn1;
        __syncthreads();                 // next K tile visible
    }

    const float rinv0 = 1.0f / l0;
    const float rinv1 = 1.0f / l1;

    float oacc[8][4];
    #pragma unroll
    for (int nt = 0; nt < 8; ++nt)
        #pragma unroll
        for (int i = 0; i < 4; ++i) oacc[nt][i] = 0.0f;

    // preload K0 and V0 for pass 2
    {
        float4 kreg[4];
        load_regs<4>(kbase, kreg, tid);
        store_split<4>(kreg, smem + OFF_KH, smem + OFF_KL, 1.0f, tid);
        float4 vreg[4];
        load_regs<4>(vbase, vreg, tid);
        store_split<4>(vreg, smem + OFF_VH, smem + OFF_VL, 1.0f, tid);
    }
    __syncthreads();

    // ============ PASS 2: recompute S, mask from bits, write probs, O += P V ============
    for (int kt = 0; kt < 32; ++kt) {
        const int k0 = kt * 64;

        float4 knext[4], vnext[4];
        if (kt + 1 < 32) {
            load_regs<4>(kbase + (size_t)(k0 + 64) * DD, knext, tid);
            load_regs<4>(vbase + (size_t)(k0 + 64) * DD, vnext, tid);
        }
        const size_t pbase = (size_t)kt * (NROWS * 4);
        const uint32_t w0 = g_packed[pbase + pc0];
        const uint32_t w1 = g_packed[pbase + pc1];

        #pragma unroll
        for (int h = 0; h < 2; ++h) {
            float sacc[4][4];
            #pragma unroll
            for (int i = 0; i < 4; ++i)
                #pragma unroll
                for (int j = 0; j < 4; ++j) sacc[i][j] = 0.0f;

            #pragma unroll
            for (int kc = 0; kc < 4; ++kc) {
                uint32_t ah[4], al[4];
                ldsm4(qh_a + kc * 32, ah);
                ldsm4(ql_a + kc * 32, al);
                #pragma unroll
                for (int pp = 0; pp < 2; ++pp) {
                    const int p = 2 * h + pp;
                    uint32_t kh4[4], kl4[4];
                    ldsm4(kh_a + p * 16 * STRIDE + kc * 32, kh4);
                    ldsm4(kl_a + p * 16 * STRIDE + kc * 32, kl4);
                    mma_bf16(sacc[2 * pp],     ah, kh4[0], kh4[1]);
                    mma_bf16(sacc[2 * pp],     ah, kl4[0], kl4[1]);
                    mma_bf16(sacc[2 * pp],     al, kh4[0], kh4[1]);
                    mma_bf16(sacc[2 * pp + 1], ah, kh4[2], kh4[3]);
                    mma_bf16(sacc[2 * pp + 1], ah, kl4[2], kl4[3]);
                    mma_bf16(sacc[2 * pp + 1], al, kh4[2], kh4[3]);
                }
            }

            // mask + exp + write probs + build P fragments
            uint32_t ph2[2][4], pl2[2][4];
            #pragma unroll
            for (int nt2 = 0; nt2 < 4; ++nt2) {
                const int nt = 4 * h + nt2;
                const int sh = nt * 4;
                float s0 = sacc[nt2][0], s1 = sacc[nt2][1];
                float s2 = sacc[nt2][2], s3 = sacc[nt2][3];
                apply_bits(w0 >> sh, s0, s1);
                apply_bits(w1 >> sh, s2, s3);
                float p00 = __expf(s0 - m0) * rinv0;
                float p01 = __expf(s1 - m0) * rinv0;
                float p10 = __expf(s2 - m1) * rinv1;
                float p11 = __expf(s3 - m1) * rinv1;
                const int cb = k0 + nt * 8 + qt * 2;
                *reinterpret_cast<float2*>(a0p + cb) = make_float2(p00, p01);
                *reinterpret_cast<float2*>(a1p + cb) = make_float2(p10, p11);
                const int kc2 = nt2 >> 1;
                if ((nt2 & 1) == 0) {
                    split2(p00, p01, ph2[kc2][0], pl2[kc2][0]);   // row0, k-lo
                    split2(p10, p11, ph2[kc2][1], pl2[kc2][1]);   // row1, k-lo
                } else {
                    split2(p00, p01, ph2[kc2][2], pl2[kc2][2]);   // row0, k-hi
                    split2(p10, p11, ph2[kc2][3], pl2[kc2][3]);   // row1, k-hi
                }
            }

            // O += P(:, h*32..h*32+31) @ V(h*32..h*32+31, :)
            #pragma unroll
            for (int kc2 = 0; kc2 < 2; ++kc2) {
                const int krow = h * 32 + kc2 * 16;
                #pragma unroll
                for (int p = 0; p < 4; ++p) {
                    uint32_t vh4[4], vl4[4];
                    ldsm4t(vh_a + krow * STRIDE + p * 32, vh4);
                    ldsm4t(vl_a + krow * STRIDE + p * 32, vl4);
                    mma_bf16(oacc[2 * p],     ph2[kc2], vh4[0], vh4[1]);
                    mma_bf16(oacc[2 * p],     ph2[kc2], vl4[0], vl4[1]);
                    mma_bf16(oacc[2 * p],     pl2[kc2], vh4[0], vh4[1]);
                    mma_bf16(oacc[2 * p + 1], ph2[kc2], vh4[2], vh4[3]);
                    mma_bf16(oacc[2 * p + 1], ph2[kc2], vl4[2], vl4[3]);
                    mma_bf16(oacc[2 * p + 1], pl2[kc2], vh4[2], vh4[3]);
                }
            }
        }
        __syncthreads();                 // all warps done reading K/V smem
        if (kt + 1 < 32) {
            store_split<4>(knext, smem + OFF_KH, smem + OFF_KL, 1.0f, tid);
            store_split<4>(vnext, smem + OFF_VH, smem + OFF_VL, 1.0f, tid);
        }
        __syncthreads();                 // next tiles visible
    }

    // ---- write output ----
    float* o0 = outp + g0 * DD;
    float* o1 = o0 + (size_t)8 * DD;
    #pragma unroll
    for (int nt = 0; nt < 8; ++nt) {
        const int cb = nt * 8 + qt * 2;
        *reinterpret_cast<float2*>(o0 + cb) = make_float2(oacc[nt][0], oacc[nt][1]);
        *reinterpret_cast<float2*>(o1 + cb) = make_float2(oacc[nt][2], oacc[nt][3]);
    }
}

extern "C" void kernel_launch(void* const* d_in, const int* in_sizes, int n_in,
                              void* d_out, int out_size)
{
    const float* q    = (const float*)d_in[0];
    const float* k    = (const float*)d_in[1];
    const float* v    = (const float*)d_in[2];
    const int*   diag = (const int*)d_in[3];
    const int*   mask = (const int*)d_in[4];

    float* out  = (float*)d_out;                     // [B, L, D]
    float* attn = out + (size_t)BB * LLEN * DD;      // [B, L, L]

    cudaFuncSetAttribute(attn_mma_kernel,
                         cudaFuncAttributeMaxDynamicSharedMemorySize, SMEM_TOTAL);
    dim3 grid(LLEN / TQ, BB);
    attn_mma_kernel<<<grid, NTH, SMEM_TOTAL>>>(q, k, v, diag, mask, out, attn);
}

// round 7
// speedup vs baseline: 1.0415x; 1.0204x over previous
#include <cuda_runtime.h>
#include <cuda_bf16.h>
#include <stdint.h>

#define BB 16
#define LLEN 2048
#define DD 64
#define TQ 128
#define NTH 256
#define STRIDE 144                  // smem row stride bytes (72 bf16, conflict-free)
#define BUFB (64 * STRIDE)          // one 64-row half (hi or lo) = 9216 B
#define TILEB (2 * BUFB)            // hi+lo buffer = 18432 B

#define OFF_V 0                     // region A: V double buffer (pass 2)
#define OFF_K (2 * TILEB)           // region B: K double buffer (pass 1)
#define SMEM_TOTAL (4 * TILEB)      // 73728 B

#define NEG_INF __int_as_float(0xff800000)

// ---------------- helpers ----------------
__device__ __forceinline__ uint32_t smem_u32(const void* p) {
    uint32_t a;
    asm("{ .reg .u64 t; cvta.to.shared.u64 t, %1; cvt.u32.u64 %0, t; }" : "=r"(a) : "l"(p));
    return a;
}
__device__ __forceinline__ void ldsm4(uint32_t a, uint32_t r[4]) {
    asm volatile("ldmatrix.sync.aligned.m8n8.x4.shared.b16 {%0,%1,%2,%3}, [%4];"
                 : "=r"(r[0]), "=r"(r[1]), "=r"(r[2]), "=r"(r[3]) : "r"(a));
}
__device__ __forceinline__ void ldsm4t(uint32_t a, uint32_t r[4]) {
    asm volatile("ldmatrix.sync.aligned.m8n8.x4.trans.shared.b16 {%0,%1,%2,%3}, [%4];"
                 : "=r"(r[0]), "=r"(r[1]), "=r"(r[2]), "=r"(r[3]) : "r"(a));
}
__device__ __forceinline__ void mma_bf16(float* d, const uint32_t* a, uint32_t b0, uint32_t b1) {
    asm volatile("mma.sync.aligned.m16n8k16.row.col.f32.bf16.bf16.f32 "
                 "{%0,%1,%2,%3}, {%4,%5,%6,%7}, {%8,%9}, {%0,%1,%2,%3};"
                 : "+f"(d[0]), "+f"(d[1]), "+f"(d[2]), "+f"(d[3])
                 : "r"(a[0]), "r"(a[1]), "r"(a[2]), "r"(a[3]), "r"(b0), "r"(b1));
}
__device__ __forceinline__ void split2(float a, float b, uint32_t& hi, uint32_t& lo) {
    __nv_bfloat16 ah = __float2bfloat16(a);
    __nv_bfloat16 bh = __float2bfloat16(b);
    float ar = a - __bfloat162float(ah);
    float br = b - __bfloat162float(bh);
    __nv_bfloat162 H; H.x = ah; H.y = bh;
    __nv_bfloat162 L; L.x = __float2bfloat16(ar); L.y = __float2bfloat16(br);
    hi = *reinterpret_cast<uint32_t*>(&H);
    lo = *reinterpret_cast<uint32_t*>(&L);
}
__device__ __forceinline__ void load_regs4(const float* __restrict__ g, float4* r, int tid) {
    #pragma unroll
    for (int i = 0; i < 4; ++i)
        r[i] = reinterpret_cast<const float4*>(g)[tid + i * NTH];
}
__device__ __forceinline__ void store_split4(const float4* r, char* hi, char* lo, int tid) {
    #pragma unroll
    for (int i = 0; i < 4; ++i) {
        int idx = tid + i * NTH;
        float4 t = r[i];
        uint32_t h01, l01, h23, l23;
        split2(t.x, t.y, h01, l01);
        split2(t.z, t.w, h23, l23);
        int rr = idx >> 4;
        int c8 = (idx & 15) << 3;
        *reinterpret_cast<uint2*>(hi + rr * STRIDE + c8) = make_uint2(h01, h23);
        *reinterpret_cast<uint2*>(lo + rr * STRIDE + c8) = make_uint2(l01, l23);
    }
}

__global__ __launch_bounds__(NTH, 2)
void attn_mma_kernel(const float* __restrict__ qg,
                     const float* __restrict__ kg,
                     const float* __restrict__ vg,
                     const int* __restrict__ diag,
                     const int* __restrict__ maskb,
                     float* __restrict__ outp,
                     float* __restrict__ attn)
{
    extern __shared__ __align__(16) char smem[];
    const int tid  = threadIdx.x;
    const int wid  = tid >> 5;
    const int lane = tid & 31;
    const int qt   = lane & 3;
    const int b    = blockIdx.y;
    const int q0   = blockIdx.x * TQ;

    const uint32_t sb = smem_u32(smem);
    const float* kbase = kg + (size_t)b * LLEN * DD;
    const float* vbase = vg + (size_t)b * LLEN * DD;

    const int r0l = wid * 16 + (lane >> 2);          // this thread's row0 (row1 = +8)
    const size_t g0 = (size_t)b * LLEN + q0 + r0l;
    const int* m0p = maskb + g0 * LLEN;
    const int* m1p = m0p + (size_t)8 * LLEN;
    const int* d0p = diag + g0 * LLEN;
    const int* d1p = d0p + (size_t)8 * LLEN;
    float* a0p = attn + g0 * LLEN;
    float* a1p = a0p + (size_t)8 * LLEN;

    // ---- Q fragments loaded straight from global into registers (scaled 1/8) ----
    uint32_t qfh[16], qfl[16];
    {
        const float* q0p = qg + g0 * DD;
        const float* q1p = q0p + 8 * DD;
        #pragma unroll
        for (int kc = 0; kc < 4; ++kc) {
            const int c = kc * 16 + qt * 2;
            float2 x0 = *reinterpret_cast<const float2*>(q0p + c);
            float2 x1 = *reinterpret_cast<const float2*>(q1p + c);
            float2 x2 = *reinterpret_cast<const float2*>(q0p + c + 8);
            float2 x3 = *reinterpret_cast<const float2*>(q1p + c + 8);
            split2(x0.x * 0.125f, x0.y * 0.125f, qfh[4 * kc + 0], qfl[4 * kc + 0]);
            split2(x1.x * 0.125f, x1.y * 0.125f, qfh[4 * kc + 1], qfl[4 * kc + 1]);
            split2(x2.x * 0.125f, x2.y * 0.125f, qfh[4 * kc + 2], qfl[4 * kc + 2]);
            split2(x3.x * 0.125f, x3.y * 0.125f, qfh[4 * kc + 3], qfl[4 * kc + 3]);
        }
    }

    // ldmatrix per-lane address components (relative to buffer base)
    const uint32_t boff = (uint32_t)(((((lane >> 4) & 1) * 8) + (lane & 7)) * STRIDE
                                     + ((lane >> 3) & 1) * 16);
    const uint32_t voff = (uint32_t)(((((lane >> 3) & 1) * 8) + (lane & 7)) * STRIDE
                                     + ((lane >> 4) & 1) * 16);

    // preload K tile 0 and V tile 0 (separate regions, both buffer 0)
    {
        float4 r[4];
        load_regs4(kbase, r, tid);
        store_split4(r, smem + OFF_K, smem + OFF_K + BUFB, tid);
        float4 s[4];
        load_regs4(vbase, s, tid);
        store_split4(s, smem + OFF_V, smem + OFF_V + BUFB, tid);
    }

    float m0 = -3.0e38f, m1 = -3.0e38f, l0 = 0.0f, l1 = 0.0f;

    // ============ PASS 1: S = QK^T, masks, raw-score write, online stats ============
    for (int kt = 0; kt < 32; ++kt) {
        const int k0 = kt * 64;
        float4 knext[4];
        if (kt + 1 < 32)
            load_regs4(kbase + (size_t)(k0 + 64) * DD, knext, tid);
        __syncthreads();                 // buf[kt&1] visible; prior readers done

        const int pb = kt & 1;
        const uint32_t kh_a = sb + OFF_K + pb * TILEB + boff;
        const uint32_t kl_a = kh_a + BUFB;

        float acc[8][4];
        #pragma unroll
        for (int nt = 0; nt < 8; ++nt)
            #pragma unroll
            for (int i = 0; i < 4; ++i) acc[nt][i] = 0.0f;

        #pragma unroll
        for (int kc = 0; kc < 4; ++kc) {
            #pragma unroll
            for (int p = 0; p < 4; ++p) {
                uint32_t kh4[4], kl4[4];
                ldsm4(kh_a + p * 16 * STRIDE + kc * 32, kh4);
                ldsm4(kl_a + p * 16 * STRIDE + kc * 32, kl4);
                mma_bf16(acc[2 * p],     qfh + 4 * kc, kh4[0], kh4[1]);
                mma_bf16(acc[2 * p],     qfh + 4 * kc, kl4[0], kl4[1]);
                mma_bf16(acc[2 * p],     qfl + 4 * kc, kh4[0], kh4[1]);
                mma_bf16(acc[2 * p + 1], qfh + 4 * kc, kh4[2], kh4[3]);
                mma_bf16(acc[2 * p + 1], qfh + 4 * kc, kl4[2], kl4[3]);
                mma_bf16(acc[2 * p + 1], qfl + 4 * kc, kh4[2], kh4[3]);
            }
        }
        if (kt + 1 < 32)
            store_split4(knext, smem + OFF_K + (pb ^ 1) * TILEB,
                         smem + OFF_K + (pb ^ 1) * TILEB + BUFB, tid);

        // ---- epilogue: masks row0 then row1, raw-score writes, stats ----
        float t0 = -3.0e38f, t1 = -3.0e38f;
        {
            int2 M[8], D2[8];
            #pragma unroll
            for (int nt = 0; nt < 8; ++nt) {
                const int cb = k0 + nt * 8 + qt * 2;
                M[nt]  = *reinterpret_cast<const int2*>(m0p + cb);
                D2[nt] = *reinterpret_cast<const int2*>(d0p + cb);
            }
            #pragma unroll
            for (int nt = 0; nt < 8; ++nt) {
                float s0 = acc[nt][0], s1 = acc[nt][1];
                if (M[nt].x)       s0 = NEG_INF;
                if (D2[nt].x == 0) s0 = -1.0e32f;
                if (M[nt].y)       s1 = NEG_INF;
                if (D2[nt].y == 0) s1 = -1.0e32f;
                *reinterpret_cast<float2*>(a0p + k0 + nt * 8 + qt * 2) = make_float2(s0, s1);
                acc[nt][0] = s0; acc[nt][1] = s1;
                t0 = fmaxf(t0, fmaxf(s0, s1));
            }
        }
        {
            int2 M[8], D2[8];
            #pragma unroll
            for (int nt = 0; nt < 8; ++nt) {
                const int cb = k0 + nt * 8 + qt * 2;
                M[nt]  = *reinterpret_cast<const int2*>(m1p + cb);
                D2[nt] = *reinterpret_cast<const int2*>(d1p + cb);
            }
            #pragma unroll
            for (int nt = 0; nt < 8; ++nt) {
                float s2 = acc[nt][2], s3 = acc[nt][3];
                if (M[nt].x)       s2 = NEG_INF;
                if (D2[nt].x == 0) s2 = -1.0e32f;
                if (M[nt].y)       s3 = NEG_INF;
                if (D2[nt].y == 0) s3 = -1.0e32f;
                *reinterpret_cast<float2*>(a1p + k0 + nt * 8 + qt * 2) = make_float2(s2, s3);
                acc[nt][2] = s2; acc[nt][3] = s3;
                t1 = fmaxf(t1, fmaxf(s2, s3));
            }
        }
        t0 = fmaxf(t0, __shfl_xor_sync(0xffffffffu, t0, 1));
        t0 = fmaxf(t0, __shfl_xor_sync(0xffffffffu, t0, 2));
        t1 = fmaxf(t1, __shfl_xor_sync(0xffffffffu, t1, 1));
        t1 = fmaxf(t1, __shfl_xor_sync(0xffffffffu, t1, 2));
        const float mn0 = fmaxf(m0, t0);
        const float mn1 = fmaxf(m1, t1);
        float e0 = 0.0f, e1 = 0.0f;
        #pragma unroll
        for (int nt = 0; nt < 8; ++nt) {
            e0 += __expf(acc[nt][0] - mn0) + __expf(acc[nt][1] - mn0);
            e1 += __expf(acc[nt][2] - mn1) + __expf(acc[nt][3] - mn1);
        }
        e0 += __shfl_xor_sync(0xffffffffu, e0, 1);
        e0 += __shfl_xor_sync(0xffffffffu, e0, 2);
        e1 += __shfl_xor_sync(0xffffffffu, e1, 1);
        e1 += __shfl_xor_sync(0xffffffffu, e1, 2);
        l0 = l0 * __expf(m0 - mn0) + e0;  m0 = mn0;
        l1 = l1 * __expf(m1 - mn1) + e1;  m1 = mn1;
    }

    const float rinv0 = 1.0f / l0;
    const float rinv1 = 1.0f / l1;

    float oacc[8][4];
    #pragma unroll
    for (int nt = 0; nt < 8; ++nt)
        #pragma unroll
        for (int i = 0; i < 4; ++i) oacc[nt][i] = 0.0f;

    // ============ PASS 2: readback scores, probs write, O += P V ============
    for (int kt = 0; kt < 32; ++kt) {
        const int k0 = kt * 64;
        float4 vnext[4];
        if (kt + 1 < 32)
            load_regs4(vbase + (size_t)(k0 + 64) * DD, vnext, tid);

        // score loads for THIS tile (same-thread data from pass 1) — issue pre-barrier
        float2 sx0[4], sy0[4], sx1[4], sy1[4];
        #pragma unroll
        for (int kc2 = 0; kc2 < 4; ++kc2) {
            const int cA = k0 + kc2 * 16 + qt * 2;
            sx0[kc2] = *reinterpret_cast<const float2*>(a0p + cA);
            sy0[kc2] = *reinterpret_cast<const float2*>(a0p + cA + 8);
            sx1[kc2] = *reinterpret_cast<const float2*>(a1p + cA);
            sy1[kc2] = *reinterpret_cast<const float2*>(a1p + cA + 8);
        }
        __syncthreads();                 // V buf[kt&1] visible; prior readers done

        // exp + probs write + P fragments
        uint32_t ph[16], pl[16];
        #pragma unroll
        for (int kc2 = 0; kc2 < 4; ++kc2) {
            const int cA = k0 + kc2 * 16 + qt * 2;
            float p00 = __expf(sx0[kc2].x - m0) * rinv0;
            float p01 = __expf(sx0[kc2].y - m0) * rinv0;
            float p02 = __expf(sy0[kc2].x - m0) * rinv0;
            float p03 = __expf(sy0[kc2].y - m0) * rinv0;
            float p10 = __expf(sx1[kc2].x - m1) * rinv1;
            float p11 = __expf(sx1[kc2].y - m1) * rinv1;
            float p12 = __expf(sy1[kc2].x - m1) * rinv1;
            float p13 = __expf(sy1[kc2].y - m1) * rinv1;
            *reinterpret_cast<float2*>(a0p + cA)     = make_float2(p00, p01);
            *reinterpret_cast<float2*>(a0p + cA + 8) = make_float2(p02, p03);
            *reinterpret_cast<float2*>(a1p + cA)     = make_float2(p10, p11);
            *reinterpret_cast<float2*>(a1p + cA + 8) = make_float2(p12, p13);
            split2(p00, p01, ph[4 * kc2 + 0], pl[4 * kc2 + 0]);   // row0, k-lo
            split2(p10, p11, ph[4 * kc2 + 1], pl[4 * kc2 + 1]);   // row1, k-lo
            split2(p02, p03, ph[4 * kc2 + 2], pl[4 * kc2 + 2]);   // row0, k-hi
            split2(p12, p13, ph[4 * kc2 + 3], pl[4 * kc2 + 3]);   // row1, k-hi
        }

        const int pb = kt & 1;
        const uint32_t vh_a = sb + OFF_V + pb * TILEB + voff;
        const uint32_t vl_a = vh_a + BUFB;
        #pragma unroll
        for (int kc2 = 0; kc2 < 4; ++kc2) {
            #pragma unroll
            for (int p = 0; p < 4; ++p) {
                uint32_t vh4[4], vl4[4];
                ldsm4t(vh_a + kc2 * 16 * STRIDE + p * 32, vh4);
                ldsm4t(vl_a + kc2 * 16 * STRIDE + p * 32, vl4);
                mma_bf16(oacc[2 * p],     ph + 4 * kc2, vh4[0], vh4[1]);
                mma_bf16(oacc[2 * p],     ph + 4 * kc2, vl4[0], vl4[1]);
                mma_bf16(oacc[2 * p],     pl + 4 * kc2, vh4[0], vh4[1]);
                mma_bf16(oacc[2 * p + 1], ph + 4 * kc2, vh4[2], vh4[3]);
                mma_bf16(oacc[2 * p + 1], ph + 4 * kc2, vl4[2], vl4[3]);
                mma_bf16(oacc[2 * p + 1], pl + 4 * kc2, vh4[2], vh4[3]);
            }
        }
        if (kt + 1 < 32)
            store_split4(vnext, smem + OFF_V + (pb ^ 1) * TILEB,
                         smem + OFF_V + (pb ^ 1) * TILEB + BUFB, tid);
    }

    // ---- write output ----
    float* o0 = outp + g0 * DD;
    float* o1 = o0 + (size_t)8 * DD;
    #pragma unroll
    for (int nt = 0; nt < 8; ++nt) {
        const int cb = nt * 8 + qt * 2;
        *reinterpret_cast<float2*>(o0 + cb) = make_float2(oacc[nt][0], oacc[nt][1]);
        *reinterpret_cast<float2*>(o1 + cb) = make_float2(oacc[nt][2], oacc[nt][3]);
    }
}

extern "C" void kernel_launch(void* const* d_in, const int* in_sizes, int n_in,
                              void* d_out, int out_size)
{
    const float* q    = (const float*)d_in[0];
    const float* k    = (const float*)d_in[1];
    const float* v    = (const float*)d_in[2];
    const int*   diag = (const int*)d_in[3];
    const int*   mask = (const int*)d_in[4];

    float* out  = (float*)d_out;                     // [B, L, D]
    float* attn = out + (size_t)BB * LLEN * DD;      // [B, L, L]

    cudaFuncSetAttribute(attn_mma_kernel,
                         cudaFuncAttributeMaxDynamicSharedMemorySize, SMEM_TOTAL);
    dim3 grid(LLEN / TQ, BB);
    attn_mma_kernel<<<grid, NTH, SMEM_TOTAL>>>(q, k, v, diag, mask, out, attn);
}